// round 1
// baseline (speedup 1.0000x reference)
#include <cuda_runtime.h>
#include <cstddef>

// Problem constants (from reference)
#define BATCH     131072
#define N_FACTORS 64
#define RATING_LO 1.0f
#define RATING_HI 5.0f

// One warp per batch row.
// Lane l loads float2 p[2l..2l+1], q[2l..2l+1]  (32 lanes x 8B = 256B per row, coalesced).
// Butterfly-reduce the dot product; lane 0 writes predict; all lanes write features.
__global__ __launch_bounds__(256, 8)
void svd_predict_kernel(const int2*  __restrict__ user_item,   // [BATCH] (uid, iid)
                        const float* __restrict__ pu,          // [N_USERS, 64]
                        const float* __restrict__ qi,          // [N_ITEMS, 64]
                        const float* __restrict__ bu,          // [N_USERS]
                        const float* __restrict__ bi,          // [N_ITEMS]
                        const float* __restrict__ gmean,       // scalar
                        float*       __restrict__ out)         // [BATCH] predict ++ [BATCH,128] feats
{
    const int warp_id = (blockIdx.x * blockDim.x + threadIdx.x) >> 5;
    const int lane    = threadIdx.x & 31;
    if (warp_id >= BATCH) return;

    const int2 ui = __ldg(&user_item[warp_id]);   // x = uid, y = iid
    const size_t uoff = (size_t)ui.x * N_FACTORS;
    const size_t ioff = (size_t)ui.y * N_FACTORS;

    const float2 pv = __ldg((const float2*)(pu + uoff) + lane);
    const float2 qv = __ldg((const float2*)(qi + ioff) + lane);

    float part = pv.x * qv.x + pv.y * qv.y;
    #pragma unroll
    for (int off = 16; off > 0; off >>= 1)
        part += __shfl_xor_sync(0xFFFFFFFFu, part, off);

    // features: out[BATCH + row*128 + 0..63] = p, [.. + 64..127] = q
    float* feat = out + BATCH + (size_t)warp_id * (2 * N_FACTORS);
    ((float2*)feat)[lane]                 = pv;
    ((float2*)(feat + N_FACTORS))[lane]   = qv;

    if (lane == 0) {
        float pr = gmean[0] + __ldg(&bu[ui.x]) + __ldg(&bi[ui.y]) + part;
        pr = fminf(fmaxf(pr, RATING_LO), RATING_HI);
        out[warp_id] = pr;
    }
}

extern "C" void kernel_launch(void* const* d_in, const int* in_sizes, int n_in,
                              void* d_out, int out_size)
{
    const int2*  user_item = (const int2*) d_in[0];
    const float* pu        = (const float*)d_in[1];
    const float* qi        = (const float*)d_in[2];
    const float* bu        = (const float*)d_in[3];
    const float* bi        = (const float*)d_in[4];
    const float* gmean     = (const float*)d_in[5];
    float*       out       = (float*)d_out;

    const int threads = 256;                 // 8 warps per block
    const int rows_per_block = threads / 32;
    const int blocks = (BATCH + rows_per_block - 1) / rows_per_block;
    svd_predict_kernel<<<blocks, threads>>>(user_item, pu, qi, bu, bi, gmean, out);
}

// round 4
// speedup vs baseline: 1.5863x; 1.5863x over previous
#include <cuda_runtime.h>
#include <cstddef>

#define BATCH     131072
#define N_FACTORS 64
#define RATING_LO 1.0f
#define RATING_HI 5.0f

// 4 batch rows per warp. Half-warp (16 lanes) covers one 64-float row with
// float4 lanes: one LDG.128 instruction gathers p (or q) for TWO rows at once.
// 8 independent 128-bit gathers in flight per warp (MLP=8).
__global__ __launch_bounds__(256, 8)
void svd_predict_kernel(const int2*  __restrict__ user_item,   // [BATCH] (uid, iid)
                        const float* __restrict__ pu,          // [N_USERS, 64]
                        const float* __restrict__ qi,          // [N_ITEMS, 64]
                        const float* __restrict__ bu,          // [N_USERS]
                        const float* __restrict__ bi,          // [N_ITEMS]
                        const float* __restrict__ gmean,       // scalar
                        float*       __restrict__ out)         // [BATCH] predict ++ [BATCH,128] feats
{
    const int warp_id = (blockIdx.x * blockDim.x + threadIdx.x) >> 5;
    const int lane    = threadIdx.x & 31;
    const int half    = lane >> 4;      // 0: rows base+0 / base+2,  1: rows base+1 / base+3
    const int hl      = lane & 15;      // float4 index within the 64-float row
    const int base    = warp_id * 4;

    // Four independent (broadcast) index loads — all in flight together.
    const int2 ui0 = __ldg(&user_item[base + 0]);
    const int2 ui1 = __ldg(&user_item[base + 1]);
    const int2 ui2 = __ldg(&user_item[base + 2]);
    const int2 ui3 = __ldg(&user_item[base + 3]);

    const int uidA = half ? ui1.x : ui0.x;   // row base + half
    const int iidA = half ? ui1.y : ui0.y;
    const int uidB = half ? ui3.x : ui2.x;   // row base + 2 + half
    const int iidB = half ? ui3.y : ui2.y;

    // 4 independent 128-bit gathers (each instruction covers two rows).
    const float4 pA = __ldg((const float4*)(pu + (size_t)uidA * N_FACTORS) + hl);
    const float4 qA = __ldg((const float4*)(qi + (size_t)iidA * N_FACTORS) + hl);
    const float4 pB = __ldg((const float4*)(pu + (size_t)uidB * N_FACTORS) + hl);
    const float4 qB = __ldg((const float4*)(qi + (size_t)iidB * N_FACTORS) + hl);

    float dA = pA.x * qA.x + pA.y * qA.y + pA.z * qA.z + pA.w * qA.w;
    float dB = pB.x * qB.x + pB.y * qB.y + pB.z * qB.z + pB.w * qB.w;
    #pragma unroll
    for (int off = 8; off > 0; off >>= 1) {    // xor<=8 keeps half-warps independent
        dA += __shfl_xor_sync(0xFFFFFFFFu, dA, off);
        dB += __shfl_xor_sync(0xFFFFFFFFu, dB, off);
    }

    // Feature writes: streaming (write-once, evict-first) to keep L2 for the tables.
    float* featA = out + BATCH + (size_t)(base + half)     * (2 * N_FACTORS);
    float* featB = out + BATCH + (size_t)(base + 2 + half) * (2 * N_FACTORS);
    __stcs((float4*)featA + hl,                  pA);
    __stcs((float4*)(featA + N_FACTORS) + hl,    qA);
    __stcs((float4*)featB + hl,                  pB);
    __stcs((float4*)(featB + N_FACTORS) + hl,    qB);

    if (hl == 0) {   // lanes 0 and 16: each writes two predicts
        const float g  = __ldg(gmean);
        float prA = g + __ldg(&bu[uidA]) + __ldg(&bi[iidA]) + dA;
        float prB = g + __ldg(&bu[uidB]) + __ldg(&bi[iidB]) + dB;
        out[base + half]     = fminf(fmaxf(prA, RATING_LO), RATING_HI);
        out[base + 2 + half] = fminf(fmaxf(prB, RATING_LO), RATING_HI);
    }
}

extern "C" void kernel_launch(void* const* d_in, const int* in_sizes, int n_in,
                              void* d_out, int out_size)
{
    const int2*  user_item = (const int2*) d_in[0];
    const float* pu        = (const float*)d_in[1];
    const float* qi        = (const float*)d_in[2];
    const float* bu        = (const float*)d_in[3];
    const float* bi        = (const float*)d_in[4];
    const float* gmean     = (const float*)d_in[5];
    float*       out       = (float*)d_out;

    const int threads        = 256;                 // 8 warps
    const int rows_per_block = (threads / 32) * 4;  // 32 rows per block
    const int blocks         = BATCH / rows_per_block;  // 131072 / 32 = 4096
    svd_predict_kernel<<<blocks, threads>>>(user_item, pu, qi, bu, bi, gmean, out);
}